// round 6
// baseline (speedup 1.0000x reference)
#include <cuda_runtime.h>
#include <cuda_bf16.h>

// RankingLoss: out = mean(1/(pred^2+eps)) + [ sum_{i:neg, j:pos} relu(pred_j - pred_i) ] / (n_neg*n_pos)
// DELTA = 0, EPS = 1e-5, B = 8192. target is int32 on the wire.
//
// K1 (1 block, 1024 thr): deterministic compaction of positive-labeled preds into g_pos
//     (prefix-scan scatter, sentinel-padded to a 512 multiple), plus trivial-term sum
//     (f32 per element like the reference, double accumulate) and neg count.
// K2 (grid 16x16, 256 thr): pairwise hinge over (512 i-rows per block) x (512-positive tile),
//     2 i per thread, ticket-based last-block final reduction writes the scalar.

#define B_FIXED  8192
#define K1_THREADS 1024
#define J_TILE   512
#define BLOCK    256
#define GX       16               // 8192 / 512 i per block
#define GY       16               // 16 * 512 = 8192 max positives
#define NPART    (GX * GY)

__device__ float        g_pos[B_FIXED + J_TILE];  // compacted positives + sentinel pad
__device__ int          g_npos_pad;               // padded count (multiple of J_TILE)
__device__ double       g_triv_total;
__device__ int          g_neg_total;
__device__ double       g_pair[NPART];
__device__ unsigned int g_ticket;                 // wraps -> self-resets every replay

__global__ __launch_bounds__(K1_THREADS)
void compact_kernel(const float* __restrict__ pred,
                    const int* __restrict__ target,
                    int B) {
    const int tid = threadIdx.x;
    const int lid = tid & 31;
    const int wid = tid >> 5;

    // Each thread owns 8 contiguous elements (coalesced 32B per thread).
    float p8[8];
    int   t8[8];
    const int base = tid * 8;
    {
        const float4* p4 = reinterpret_cast<const float4*>(pred + base);
        const int4*   t4 = reinterpret_cast<const int4*>(target + base);
        float4 pa = p4[0], pb = p4[1];
        int4   ta = t4[0], tb = t4[1];
        p8[0]=pa.x; p8[1]=pa.y; p8[2]=pa.z; p8[3]=pa.w;
        p8[4]=pb.x; p8[5]=pb.y; p8[6]=pb.z; p8[7]=pb.w;
        t8[0]=ta.x; t8[1]=ta.y; t8[2]=ta.z; t8[3]=ta.w;
        t8[4]=tb.x; t8[5]=tb.y; t8[6]=tb.z; t8[7]=tb.w;
    }

    int cnt = 0, neg = 0;
    double triv = 0.0;
    #pragma unroll
    for (int k = 0; k < 8; ++k) {
        cnt += (t8[k] == 1);
        neg += (t8[k] == 0);
        triv += (double)(1.0f / (p8[k] * p8[k] + 1e-5f));
    }

    // Block-wide exclusive scan of cnt (warp shfl + warp-total scan)
    int incl = cnt;
    #pragma unroll
    for (int off = 1; off < 32; off <<= 1) {
        int v = __shfl_up_sync(0xFFFFFFFFu, incl, off);
        if (lid >= off) incl += v;
    }
    __shared__ int wtot[32];
    __shared__ int woff[32];
    __shared__ int s_npos;
    if (lid == 31) wtot[wid] = incl;
    __syncthreads();
    if (wid == 0) {
        int v = (lid < K1_THREADS / 32) ? wtot[lid] : 0;
        int iv = v;
        #pragma unroll
        for (int off = 1; off < 32; off <<= 1) {
            int u = __shfl_up_sync(0xFFFFFFFFu, iv, off);
            if (lid >= off) iv += u;
        }
        woff[lid] = iv - v;   // exclusive
        if (lid == 31) s_npos = iv;
    }
    __syncthreads();

    // Deterministic scatter (global-index order preserved)
    int o = woff[wid] + incl - cnt;
    #pragma unroll
    for (int k = 0; k < 8; ++k) {
        if (t8[k] == 1) g_pos[o++] = p8[k];
    }

    // Sentinel pad to next multiple of J_TILE
    const int npos = s_npos;
    const int npos_pad = (npos + J_TILE - 1) & ~(J_TILE - 1);
    if (tid < npos_pad - npos) g_pos[npos + tid] = -1e30f;
    if (tid == 0) g_npos_pad = npos_pad;

    // Reduce trivial + neg totals
    #pragma unroll
    for (int off = 16; off > 0; off >>= 1) {
        triv += __shfl_down_sync(0xFFFFFFFFu, triv, off);
        neg  += __shfl_down_sync(0xFFFFFFFFu, neg, off);
    }
    __shared__ double tsum[32];
    __shared__ int    nsum[32];
    if (lid == 0) { tsum[wid] = triv; nsum[wid] = neg; }
    __syncthreads();
    if (tid == 0) {
        double tt = 0.0; int nn = 0;
        #pragma unroll
        for (int w = 0; w < K1_THREADS / 32; ++w) { tt += tsum[w]; nn += nsum[w]; }
        g_triv_total = tt;
        g_neg_total = nn;
    }
}

__global__ __launch_bounds__(BLOCK)
void rank_pair_kernel(const float* __restrict__ pred,
                      const int* __restrict__ target,
                      float* __restrict__ out,
                      int B) {
    __shared__ float sj[J_TILE];
    const int tid = threadIdx.x;
    const int bx  = blockIdx.x;
    const int by  = blockIdx.y;
    const int lid = tid & 31;
    const int wid = tid >> 5;

    const int npos_pad = g_npos_pad;
    const int j0 = by * J_TILE;
    const bool active_tile = (j0 < npos_pad);

    float acc0 = 0.0f, acc1 = 0.0f;
    const int i0 = bx * (2 * BLOCK) + tid;
    const int i1 = i0 + BLOCK;
    const float pi0 = pred[i0];
    const float pi1 = pred[i1];
    const bool neg0 = (target[i0] == 0);
    const bool neg1 = (target[i1] == 0);

    if (active_tile) {
        sj[tid]         = g_pos[j0 + tid];
        sj[tid + BLOCK] = g_pos[j0 + tid + BLOCK];
        __syncthreads();

        const float4* sj4 = reinterpret_cast<const float4*>(sj);
        float a0=0.f,a1=0.f,a2=0.f,a3=0.f,b0=0.f,b1=0.f,b2=0.f,b3=0.f;
        #pragma unroll 8
        for (int j = 0; j < J_TILE / 4; ++j) {
            const float4 v = sj4[j];
            a0 += fmaxf(v.x - pi0, 0.0f);
            a1 += fmaxf(v.y - pi0, 0.0f);
            a2 += fmaxf(v.z - pi0, 0.0f);
            a3 += fmaxf(v.w - pi0, 0.0f);
            b0 += fmaxf(v.x - pi1, 0.0f);
            b1 += fmaxf(v.y - pi1, 0.0f);
            b2 += fmaxf(v.z - pi1, 0.0f);
            b3 += fmaxf(v.w - pi1, 0.0f);
        }
        acc0 = (a0 + a1) + (a2 + a3);
        acc1 = (b0 + b1) + (b2 + b3);
    }
    if (!neg0) acc0 = 0.0f;
    if (!neg1) acc1 = 0.0f;

    // Block reduce in double
    double d = (double)acc0 + (double)acc1;
    #pragma unroll
    for (int off = 16; off > 0; off >>= 1)
        d += __shfl_down_sync(0xFFFFFFFFu, d, off);
    __shared__ double wsum[BLOCK / 32];
    if (lid == 0) wsum[wid] = d;
    __syncthreads();
    if (wid == 0) {
        double t = (lid < BLOCK / 32) ? wsum[lid] : 0.0;
        #pragma unroll
        for (int off = 4; off > 0; off >>= 1)
            t += __shfl_down_sync(0xFFFFFFFFu, t, off);
        if (lid == 0) g_pair[by * GX + bx] = t;
    }

    // Last-block final reduction (ticket wraps -> graph-replay safe)
    __shared__ bool s_last;
    __threadfence();
    __syncthreads();
    if (tid == 0) {
        const unsigned int total = NPART;
        const unsigned int old = atomicInc(&g_ticket, total - 1u);
        s_last = (old == total - 1u);
    }
    __syncthreads();
    if (!s_last) return;

    double lp = 0.0;
    for (int p = tid; p < NPART; p += BLOCK) lp += g_pair[p];
    #pragma unroll
    for (int off = 16; off > 0; off >>= 1)
        lp += __shfl_down_sync(0xFFFFFFFFu, lp, off);
    __shared__ double fsum[BLOCK / 32];
    if (lid == 0) fsum[wid] = lp;
    __syncthreads();
    if (tid == 0) {
        double sp = 0.0;
        #pragma unroll
        for (int w = 0; w < BLOCK / 32; ++w) sp += fsum[w];
        const double n_neg = (double)g_neg_total;
        const double n_pos = (double)B - n_neg;
        const double N = n_neg * n_pos;
        out[0] = (float)(g_triv_total / (double)B + sp / N);
    }
}

extern "C" void kernel_launch(void* const* d_in, const int* in_sizes, int n_in,
                              void* d_out, int out_size) {
    const float* pred   = (const float*)d_in[0];
    const int*   target = (const int*)d_in[1];
    float*       out    = (float*)d_out;
    const int B = in_sizes[0];   // 8192

    compact_kernel<<<1, K1_THREADS>>>(pred, target, B);
    dim3 grid(GX, GY);
    rank_pair_kernel<<<grid, BLOCK>>>(pred, target, out, B);
}

// round 7
// speedup vs baseline: 1.0540x; 1.0540x over previous
#include <cuda_runtime.h>
#include <cuda_fp16.h>

// RankingLoss: out = mean(1/(pred^2+eps)) + [ sum_{i:neg, j:pos} relu(pred_j - pred_i) ] / (n_neg*n_pos)
// DELTA = 0, EPS = 1e-5, B = 8192. target is int32 on the wire.
//
// K1 (1 block, 1024 thr): one-pass deterministic compaction of BOTH classes
//     (pos -> g_posh, neg -> g_negh, fp16), sentinel-padded to 512 multiples,
//     plus trivial-term sum (f32 per element, double accumulate) and pos count.
// K2 (grid 16x16, 256 thr): pairwise hinge in packed half2 (3 instrs / 2 pairs),
//     2 i per thread, f32 drain every 32 j, ticket-based final reduction.

#define B_FIXED     8192
#define K1_THREADS  1024
#define J_TILE      512
#define I_PER_BLOCK 512          // 256 threads x 2 i
#define BLOCK       256
#define GX          16           // covers 8192 compacted-neg slots
#define GY          16           // covers 8192 compacted-pos slots
#define NPART       (GX * GY)

__device__ __align__(16) __half g_posh[B_FIXED + J_TILE];
__device__ __align__(16) __half g_negh[B_FIXED + I_PER_BLOCK];
__device__ int          g_npos;
__device__ int          g_npos_pad;
__device__ int          g_nneg_pad;
__device__ double       g_triv_total;
__device__ double       g_pair[NPART];
__device__ unsigned int g_ticket;   // wraps -> self-resets every graph replay

__global__ __launch_bounds__(K1_THREADS)
void compact_kernel(const float* __restrict__ pred,
                    const int* __restrict__ target,
                    int B) {
    const int tid = threadIdx.x;
    const int lid = tid & 31;
    const int wid = tid >> 5;

    // 8 contiguous elements per thread
    float p8[8];
    int   t8[8];
    const int base = tid * 8;
    {
        const float4* p4 = reinterpret_cast<const float4*>(pred + base);
        const int4*   t4 = reinterpret_cast<const int4*>(target + base);
        float4 pa = p4[0], pb = p4[1];
        int4   ta = t4[0], tb = t4[1];
        p8[0]=pa.x; p8[1]=pa.y; p8[2]=pa.z; p8[3]=pa.w;
        p8[4]=pb.x; p8[5]=pb.y; p8[6]=pb.z; p8[7]=pb.w;
        t8[0]=ta.x; t8[1]=ta.y; t8[2]=ta.z; t8[3]=ta.w;
        t8[4]=tb.x; t8[5]=tb.y; t8[6]=tb.z; t8[7]=tb.w;
    }

    int cnt = 0;                 // positives in this chunk
    double triv = 0.0;
    #pragma unroll
    for (int k = 0; k < 8; ++k) {
        cnt += (t8[k] == 1);
        triv += (double)(1.0f / (p8[k] * p8[k] + 1e-5f));
    }

    // Block-wide exclusive scan of positive count
    int incl = cnt;
    #pragma unroll
    for (int off = 1; off < 32; off <<= 1) {
        int v = __shfl_up_sync(0xFFFFFFFFu, incl, off);
        if (lid >= off) incl += v;
    }
    __shared__ int wtot[32];
    __shared__ int woff[32];
    __shared__ int s_npos;
    if (lid == 31) wtot[wid] = incl;
    __syncthreads();
    if (wid == 0) {
        int v = (lid < K1_THREADS / 32) ? wtot[lid] : 0;
        int iv = v;
        #pragma unroll
        for (int off = 1; off < 32; off <<= 1) {
            int u = __shfl_up_sync(0xFFFFFFFFu, iv, off);
            if (lid >= off) iv += u;
        }
        woff[lid] = iv - v;
        if (lid == 31) s_npos = iv;
    }
    __syncthreads();

    // Deterministic scatter of both classes (global order preserved).
    // posBefore(chunk) = woff+incl-cnt; negBefore = base - posBefore.
    int opos = woff[wid] + incl - cnt;
    int oneg = base - opos;
    #pragma unroll
    for (int k = 0; k < 8; ++k) {
        const __half h = __float2half_rn(p8[k]);
        if (t8[k] == 1) g_posh[opos++] = h;
        else            g_negh[oneg++] = h;
    }

    // Sentinel pads to 512-multiples
    const int npos = s_npos;
    const int nneg = B - npos;
    const int npos_pad = (npos + J_TILE - 1) & ~(J_TILE - 1);
    const int nneg_pad = (nneg + I_PER_BLOCK - 1) & ~(I_PER_BLOCK - 1);
    if (tid < npos_pad - npos) g_posh[npos + tid] = __float2half_rn(-30000.0f);
    if (tid < nneg_pad - nneg) g_negh[nneg + tid] = __float2half_rn( 30000.0f);
    if (tid == 0) {
        g_npos = npos;
        g_npos_pad = npos_pad;
        g_nneg_pad = nneg_pad;
    }

    // Trivial-term total
    #pragma unroll
    for (int off = 16; off > 0; off >>= 1)
        triv += __shfl_down_sync(0xFFFFFFFFu, triv, off);
    __shared__ double tsum[32];
    if (lid == 0) tsum[wid] = triv;
    __syncthreads();
    if (tid == 0) {
        double tt = 0.0;
        #pragma unroll
        for (int w = 0; w < K1_THREADS / 32; ++w) tt += tsum[w];
        g_triv_total = tt;
    }
}

__global__ __launch_bounds__(BLOCK)
void rank_pair_kernel(float* __restrict__ out, int B) {
    __shared__ __align__(16) __half2 sj[J_TILE / 2];
    const int tid = threadIdx.x;
    const int bx  = blockIdx.x;
    const int by  = blockIdx.y;
    const int lid = tid & 31;
    const int wid = tid >> 5;

    const int j0 = by * J_TILE;
    const int i0 = bx * I_PER_BLOCK;
    const bool active = (j0 < g_npos_pad) && (i0 < g_nneg_pad);

    float facc = 0.0f;
    if (active) {
        // Stage j-tile: 256 half2 loads (one per thread)
        sj[tid] = reinterpret_cast<const __half2*>(g_posh)[(j0 >> 1) + tid];
        __syncthreads();

        const __half2 pa2 = __half2half2(g_negh[i0 + tid]);
        const __half2 pb2 = __half2half2(g_negh[i0 + BLOCK + tid]);
        const __half2 z2  = __float2half2_rn(0.0f);
        const uint4* sj4 = reinterpret_cast<const uint4*>(sj);

        float fa = 0.0f, fb = 0.0f;
        #pragma unroll 1
        for (int w = 0; w < J_TILE / 32; ++w) {     // 16 windows of 32 j
            __half2 A = z2, Bh = z2;
            #pragma unroll
            for (int q = 0; q < 4; ++q) {           // 4 x uint4 = 32 j
                const uint4 u = sj4[w * 4 + q];
                const __half2 v0 = *reinterpret_cast<const __half2*>(&u.x);
                const __half2 v1 = *reinterpret_cast<const __half2*>(&u.y);
                const __half2 v2 = *reinterpret_cast<const __half2*>(&u.z);
                const __half2 v3 = *reinterpret_cast<const __half2*>(&u.w);
                A  = __hadd2(A,  __hmax2(__hsub2(v0, pa2), z2));
                A  = __hadd2(A,  __hmax2(__hsub2(v1, pa2), z2));
                A  = __hadd2(A,  __hmax2(__hsub2(v2, pa2), z2));
                A  = __hadd2(A,  __hmax2(__hsub2(v3, pa2), z2));
                Bh = __hadd2(Bh, __hmax2(__hsub2(v0, pb2), z2));
                Bh = __hadd2(Bh, __hmax2(__hsub2(v1, pb2), z2));
                Bh = __hadd2(Bh, __hmax2(__hsub2(v2, pb2), z2));
                Bh = __hadd2(Bh, __hmax2(__hsub2(v3, pb2), z2));
            }
            fa += __low2float(A) + __high2float(A);     // f32 drain per 32 j
            fb += __low2float(Bh) + __high2float(Bh);
        }
        facc = fa + fb;
    }

    // Block reduce in double
    double d = (double)facc;
    #pragma unroll
    for (int off = 16; off > 0; off >>= 1)
        d += __shfl_down_sync(0xFFFFFFFFu, d, off);
    __shared__ double wsum[BLOCK / 32];
    if (lid == 0) wsum[wid] = d;
    __syncthreads();
    if (wid == 0) {
        double t = (lid < BLOCK / 32) ? wsum[lid] : 0.0;
        #pragma unroll
        for (int off = 4; off > 0; off >>= 1)
            t += __shfl_down_sync(0xFFFFFFFFu, t, off);
        if (lid == 0) g_pair[by * GX + bx] = t;
    }

    // Last-block final reduction (ticket wraps -> graph-replay safe)
    __shared__ bool s_last;
    __threadfence();
    __syncthreads();
    if (tid == 0) {
        const unsigned int total = NPART;
        const unsigned int old = atomicInc(&g_ticket, total - 1u);
        s_last = (old == total - 1u);
    }
    __syncthreads();
    if (!s_last) return;

    double lp = 0.0;
    for (int p = tid; p < NPART; p += BLOCK) lp += g_pair[p];
    #pragma unroll
    for (int off = 16; off > 0; off >>= 1)
        lp += __shfl_down_sync(0xFFFFFFFFu, lp, off);
    __shared__ double fsum[BLOCK / 32];
    if (lid == 0) fsum[wid] = lp;
    __syncthreads();
    if (tid == 0) {
        double sp = 0.0;
        #pragma unroll
        for (int w = 0; w < BLOCK / 32; ++w) sp += fsum[w];
        const double n_pos = (double)g_npos;
        const double n_neg = (double)B - n_pos;
        const double N = n_neg * n_pos;
        out[0] = (float)(g_triv_total / (double)B + sp / N);
    }
}

extern "C" void kernel_launch(void* const* d_in, const int* in_sizes, int n_in,
                              void* d_out, int out_size) {
    const float* pred   = (const float*)d_in[0];
    const int*   target = (const int*)d_in[1];
    float*       out    = (float*)d_out;
    const int B = in_sizes[0];   // 8192

    compact_kernel<<<1, K1_THREADS>>>(pred, target, B);
    dim3 grid(GX, GY);
    rank_pair_kernel<<<grid, BLOCK>>>(out, B);
}

// round 8
// speedup vs baseline: 1.7619x; 1.6717x over previous
#include <cuda_runtime.h>
#include <cuda_fp16.h>

// RankingLoss: out = mean(1/(pred^2+eps)) + [ sum_{i:neg, j:pos} relu(pred_j - pred_i) ] / (n_neg*n_pos)
// DELTA = 0, EPS = 1e-5, B = 8192. target is int32 on the wire.
//
// Single kernel, grid (32, 16), 256 threads:
//  - each block locally compacts the positives of its 512-wide j-tile into fp16 smem
//    (sentinel-padded); inner loop = hfma2_relu + hadd2 (1 instr/pair) over ~256 real positives
//  - by==0 blocks also compute the trivial term + neg count for their 256 i's
//  - ticket-based last-block reduction writes the scalar. No second kernel.

#define BLOCK     256
#define J_TILE    512
#define MAX_GX    32
#define MAX_NPART 1024

__device__ double       g_pair[MAX_NPART];
__device__ double       g_triv[MAX_GX];
__device__ int          g_negc[MAX_GX];
__device__ unsigned int g_ticket;   // wraps -> self-resets every graph replay

__global__ __launch_bounds__(BLOCK)
void rank_fused_kernel(const float* __restrict__ pred,
                       const int* __restrict__ target,
                       float* __restrict__ out,
                       int B, int npart) {
    __shared__ __align__(16) __half spos[J_TILE + 64];
    __shared__ int swtot[BLOCK / 32];
    __shared__ int swoff[BLOCK / 32];
    __shared__ int s_npos;

    const int tid = threadIdx.x;
    const int lid = tid & 31;
    const int wid = tid >> 5;
    const int bx  = blockIdx.x;
    const int by  = blockIdx.y;
    const int j0  = by * J_TILE;

    // ---- Stage j-tile (2 elements/thread) and count positives ----
    const float2 pj = reinterpret_cast<const float2*>(pred + j0)[tid];
    const int2   tj = reinterpret_cast<const int2*>(target + j0)[tid];
    const int c0 = (tj.x == 1);
    const int c1 = (tj.y == 1);
    const int cnt = c0 + c1;

    // Warp-inclusive scan of cnt
    int incl = cnt;
    #pragma unroll
    for (int off = 1; off < 32; off <<= 1) {
        int v = __shfl_up_sync(0xFFFFFFFFu, incl, off);
        if (lid >= off) incl += v;
    }
    if (lid == 31) swtot[wid] = incl;
    __syncthreads();

    // Cross-warp scan (8 values) in warp 0
    if (wid == 0) {
        int v = (lid < BLOCK / 32) ? swtot[lid] : 0;
        int iv = v;
        #pragma unroll
        for (int off = 1; off < 8; off <<= 1) {
            int u = __shfl_up_sync(0xFFFFFFFFu, iv, off);
            if (lid >= off) iv += u;
        }
        if (lid < BLOCK / 32) swoff[lid] = iv - v;
        if (lid == BLOCK / 32 - 1) s_npos = iv;
    }
    __syncthreads();

    // Deterministic scatter of positives into compacted fp16 smem
    {
        const int o = swoff[wid] + (incl - cnt);
        if (c0) spos[o] = __float2half_rn(pj.x);
        if (c1) spos[o + c0] = __float2half_rn(pj.y);
    }
    // Sentinel pad to a 64-multiple (64 halves = 8 uint4 per outer iter)
    const int npos = s_npos;
    const int npad = (npos + 63) & ~63;
    if (tid < npad - npos) spos[npos + tid] = __float2half_rn(-30000.0f);
    __syncthreads();

    // ---- i side: one i per thread ----
    const int i = bx * BLOCK + tid;
    const float pif = pred[i];
    const bool is_neg = (target[i] == 0);

    const __half2 npi2 = __float2half2_rn(-pif);
    const __half2 one2 = __float2half2_rn(1.0f);
    const __half2 z2   = __float2half2_rn(0.0f);
    const uint4* sp4 = reinterpret_cast<const uint4*>(spos);
    const int nq = npad >> 3;    // uint4 count, multiple of 8

    float facc = 0.0f;
    #pragma unroll 1
    for (int q = 0; q < nq; q += 8) {
        __half2 A = z2, C = z2;
        #pragma unroll
        for (int r = 0; r < 8; r += 2) {
            const uint4 u = sp4[q + r];
            const uint4 v = sp4[q + r + 1];
            A = __hadd2(A, __hfma2_relu(*(const __half2*)&u.x, one2, npi2));
            A = __hadd2(A, __hfma2_relu(*(const __half2*)&u.y, one2, npi2));
            A = __hadd2(A, __hfma2_relu(*(const __half2*)&u.z, one2, npi2));
            A = __hadd2(A, __hfma2_relu(*(const __half2*)&u.w, one2, npi2));
            C = __hadd2(C, __hfma2_relu(*(const __half2*)&v.x, one2, npi2));
            C = __hadd2(C, __hfma2_relu(*(const __half2*)&v.y, one2, npi2));
            C = __hadd2(C, __hfma2_relu(*(const __half2*)&v.z, one2, npi2));
            C = __hadd2(C, __hfma2_relu(*(const __half2*)&v.w, one2, npi2));
        }
        facc += (__low2float(A) + __high2float(A)) + (__low2float(C) + __high2float(C));
    }
    if (!is_neg) facc = 0.0f;

    // ---- Block reduce pair partial (double) ----
    double d = (double)facc;
    #pragma unroll
    for (int off = 16; off > 0; off >>= 1)
        d += __shfl_down_sync(0xFFFFFFFFu, d, off);
    __shared__ double wsum[BLOCK / 32];
    if (lid == 0) wsum[wid] = d;
    __syncthreads();
    if (wid == 0) {
        double t = (lid < BLOCK / 32) ? wsum[lid] : 0.0;
        #pragma unroll
        for (int off = 4; off > 0; off >>= 1)
            t += __shfl_down_sync(0xFFFFFFFFu, t, off);
        if (lid == 0) g_pair[by * gridDim.x + bx] = t;
    }

    // ---- by==0 blocks: trivial term + neg count for this i-slab ----
    if (by == 0) {
        double td = (double)(1.0f / (pif * pif + 1e-5f));
        int    nc = is_neg ? 1 : 0;
        #pragma unroll
        for (int off = 16; off > 0; off >>= 1) {
            td += __shfl_down_sync(0xFFFFFFFFu, td, off);
            nc += __shfl_down_sync(0xFFFFFFFFu, nc, off);
        }
        __shared__ double twsum[BLOCK / 32];
        __shared__ int    nwsum[BLOCK / 32];
        if (lid == 0) { twsum[wid] = td; nwsum[wid] = nc; }
        __syncthreads();
        if (wid == 0) {
            double tt = (lid < BLOCK / 32) ? twsum[lid] : 0.0;
            int    nn = (lid < BLOCK / 32) ? nwsum[lid] : 0;
            #pragma unroll
            for (int off = 4; off > 0; off >>= 1) {
                tt += __shfl_down_sync(0xFFFFFFFFu, tt, off);
                nn += __shfl_down_sync(0xFFFFFFFFu, nn, off);
            }
            if (lid == 0) { g_triv[bx] = tt; g_negc[bx] = nn; }
        }
    }

    // ---- Last-block final reduction (ticket wraps -> graph-replay safe) ----
    __shared__ bool s_last;
    __threadfence();
    __syncthreads();
    if (tid == 0) {
        const unsigned int total = (unsigned int)npart;
        const unsigned int old = atomicInc(&g_ticket, total - 1u);
        s_last = (old == total - 1u);
    }
    __syncthreads();
    if (!s_last) return;

    const int gx = gridDim.x;
    double lp = 0.0, lt = 0.0;
    int    ln = 0;
    for (int p = tid; p < npart; p += BLOCK) lp += g_pair[p];
    if (tid < gx) { lt = g_triv[tid]; ln = g_negc[tid]; }

    #pragma unroll
    for (int off = 16; off > 0; off >>= 1) {
        lp += __shfl_down_sync(0xFFFFFFFFu, lp, off);
        lt += __shfl_down_sync(0xFFFFFFFFu, lt, off);
        ln += __shfl_down_sync(0xFFFFFFFFu, ln, off);
    }
    __shared__ double fp[BLOCK / 32];
    __shared__ double ft[BLOCK / 32];
    __shared__ int    fn[BLOCK / 32];
    if (lid == 0) { fp[wid] = lp; ft[wid] = lt; fn[wid] = ln; }
    __syncthreads();
    if (tid == 0) {
        double sp = 0.0, st = 0.0;
        int    sn = 0;
        #pragma unroll
        for (int w = 0; w < BLOCK / 32; ++w) { sp += fp[w]; st += ft[w]; sn += fn[w]; }
        const double n_neg = (double)sn;
        const double n_pos = (double)B - n_neg;
        const double N = n_neg * n_pos;
        out[0] = (float)(st / (double)B + sp / N);
    }
}

extern "C" void kernel_launch(void* const* d_in, const int* in_sizes, int n_in,
                              void* d_out, int out_size) {
    const float* pred   = (const float*)d_in[0];
    const int*   target = (const int*)d_in[1];
    float*       out    = (float*)d_out;
    const int B = in_sizes[0];   // 8192

    const int gx = B / BLOCK;    // 32
    const int gy = B / J_TILE;   // 16
    dim3 grid(gx, gy);
    rank_fused_kernel<<<grid, BLOCK>>>(pred, target, out, B, gx * gy);
}